// round 1
// baseline (speedup 1.0000x reference)
#include <cuda_runtime.h>
#include <math.h>

// Shapes are fixed by the problem.
#define ENCD   1024
#define BATCH  32
#define SEQ    2048
#define MTOT   (BATCH * SEQ)   // 65536
#define NTILES 8               // 1024 / 128 column tiles of the score GEMM

// Scratch (static device arrays: no allocation allowed).
__device__ float g_q[BATCH * ENCD];            // q'[b][e] = dec@w2 + b2 + b1
__device__ float g_partials[NTILES * MTOT];    // per-(ntile) partial scores
__device__ float g_attn[MTOT];                 // softmax weights

// ---------------------------------------------------------------------------
// K1: q'[b][e] = sum_d dec[b,d] * w2[d,e] + b2[e] + b1[e]
// grid 32 (one block per batch), 256 threads, each thread 4 outputs.
// ---------------------------------------------------------------------------
__global__ __launch_bounds__(256)
void k1_query(const float* __restrict__ dec, const float* __restrict__ w2,
              const float* __restrict__ b1, const float* __restrict__ b2) {
    __shared__ float sdec[ENCD];
    const int b = blockIdx.x;
    for (int i = threadIdx.x; i < ENCD; i += 256) sdec[i] = dec[b * ENCD + i];
    __syncthreads();

    float acc[4] = {0.f, 0.f, 0.f, 0.f};
    const int e0 = threadIdx.x;
    for (int d = 0; d < ENCD; d++) {
        const float dv = sdec[d];
        const float* wrow = w2 + (size_t)d * ENCD;
        #pragma unroll
        for (int c = 0; c < 4; c++) acc[c] += dv * wrow[e0 + 256 * c];
    }
    #pragma unroll
    for (int c = 0; c < 4; c++) {
        const int e = e0 + 256 * c;
        g_q[b * ENCD + e] = acc[c] + b1[e] + b2[e];
    }
}

// ---------------------------------------------------------------------------
// K2: fused score GEMM.
//   For C-tile [128 rows (b,s)] x [128 cols e]:
//     C = enc_tile @ w1_tile          (K = 1024, double-buffered smem, 8x8 uT)
//     partial[row] = sum_col tanh(C + q'[b][col]) * v[col]
//   written (no atomics) to g_partials[ntile][m].
// grid (512, 8), 256 threads.
// ---------------------------------------------------------------------------
__global__ __launch_bounds__(256, 2)
void k2_scores(const float* __restrict__ enc, const float* __restrict__ w1,
               const float* __restrict__ v) {
    __shared__ float As[2][16][128];   // A^T: [k][m]
    __shared__ float Bs[2][16][128];   // [k][n]
    __shared__ float qs[128], vs[128], sred[128];

    const int m0 = blockIdx.x * 128;
    const int nt = blockIdx.y;
    const int n0 = nt * 128;
    const int b  = m0 / SEQ;           // SEQ % 128 == 0 -> single batch per tile
    const int t  = threadIdx.x;
    const int tx = t & 15;             // n direction (8 cols each)
    const int ty = t >> 4;             // m direction (8 rows each)

    if (t < 128) {
        qs[t] = g_q[b * ENCD + n0 + t];
        vs[t] = v[n0 + t];
    }

    // A loads: 512 float4 per stage; thread t takes f = t and f = t+256.
    // f -> row = f>>2, kpart = f&3 (k = k0 + kpart*4).
    const int arow0 = t >> 2,        akp = t & 3;
    const int arow1 = (t + 256) >> 2;
    const float4* encv = (const float4*)(enc + (size_t)m0 * ENCD);
    // B loads: f -> krow = f>>5, nv = f&31.
    const int bkr0 = t >> 5,         bnv = t & 31;
    const int bkr1 = bkr0 + 8;
    const float4* w1v = (const float4*)w1;
    const int ncol4 = (n0 >> 2) + bnv;

    float acc[8][8];
    #pragma unroll
    for (int i = 0; i < 8; i++)
        #pragma unroll
        for (int j = 0; j < 8; j++) acc[i][j] = 0.f;

    // prologue: stage 0
    {
        float4 ra0 = encv[arow0 * 256 + akp];
        float4 ra1 = encv[arow1 * 256 + akp];
        float4 rb0 = w1v[(size_t)bkr0 * 256 + ncol4];
        float4 rb1 = w1v[(size_t)bkr1 * 256 + ncol4];
        As[0][akp * 4 + 0][arow0] = ra0.x; As[0][akp * 4 + 1][arow0] = ra0.y;
        As[0][akp * 4 + 2][arow0] = ra0.z; As[0][akp * 4 + 3][arow0] = ra0.w;
        As[0][akp * 4 + 0][arow1] = ra1.x; As[0][akp * 4 + 1][arow1] = ra1.y;
        As[0][akp * 4 + 2][arow1] = ra1.z; As[0][akp * 4 + 3][arow1] = ra1.w;
        *(float4*)&Bs[0][bkr0][bnv * 4] = rb0;
        *(float4*)&Bs[0][bkr1][bnv * 4] = rb1;
    }
    __syncthreads();

    int cur = 0;
    for (int ks = 0; ks < 64; ks++) {
        float4 na0, na1, nb0, nb1;
        const int k0n = (ks + 1) * 16;
        if (ks < 63) {
            na0 = encv[arow0 * 256 + (k0n >> 2) + akp];
            na1 = encv[arow1 * 256 + (k0n >> 2) + akp];
            nb0 = w1v[(size_t)(k0n + bkr0) * 256 + ncol4];
            nb1 = w1v[(size_t)(k0n + bkr1) * 256 + ncol4];
        }
        #pragma unroll
        for (int kk = 0; kk < 16; kk++) {
            float a[8], bb[8];
            *(float4*)&a[0]  = *(const float4*)&As[cur][kk][ty * 8];
            *(float4*)&a[4]  = *(const float4*)&As[cur][kk][ty * 8 + 4];
            *(float4*)&bb[0] = *(const float4*)&Bs[cur][kk][tx * 8];
            *(float4*)&bb[4] = *(const float4*)&Bs[cur][kk][tx * 8 + 4];
            #pragma unroll
            for (int i = 0; i < 8; i++)
                #pragma unroll
                for (int j = 0; j < 8; j++)
                    acc[i][j] += a[i] * bb[j];
        }
        if (ks < 63) {
            const int nxt = cur ^ 1;
            As[nxt][akp * 4 + 0][arow0] = na0.x; As[nxt][akp * 4 + 1][arow0] = na0.y;
            As[nxt][akp * 4 + 2][arow0] = na0.z; As[nxt][akp * 4 + 3][arow0] = na0.w;
            As[nxt][akp * 4 + 0][arow1] = na1.x; As[nxt][akp * 4 + 1][arow1] = na1.y;
            As[nxt][akp * 4 + 2][arow1] = na1.z; As[nxt][akp * 4 + 3][arow1] = na1.w;
            *(float4*)&Bs[nxt][bkr0][bnv * 4] = nb0;
            *(float4*)&Bs[nxt][bkr1][bnv * 4] = nb1;
            __syncthreads();
            cur = nxt;
        }
    }

    // Epilogue: tanh + dot with v, reduce 8 cols locally then across the
    // 16 lanes (tx) that share this ty via xor-shuffles (width-16 groups).
    float pr[8];
    #pragma unroll
    for (int i = 0; i < 8; i++) {
        float s = 0.f;
        #pragma unroll
        for (int j = 0; j < 8; j++) {
            const float c = acc[i][j] + qs[tx * 8 + j];
            s += tanhf(c) * vs[tx * 8 + j];
        }
        pr[i] = s;
    }
    #pragma unroll
    for (int off = 8; off > 0; off >>= 1)
        #pragma unroll
        for (int i = 0; i < 8; i++)
            pr[i] += __shfl_xor_sync(0xffffffffu, pr[i], off);
    if (tx == 0) {
        #pragma unroll
        for (int i = 0; i < 8; i++) sred[ty * 8 + i] = pr[i];
    }
    __syncthreads();
    if (t < 128)
        g_partials[(size_t)nt * MTOT + m0 + t] = sred[t];
}

// ---------------------------------------------------------------------------
// K3: sum the 8 column-tile partials (fixed order -> deterministic),
//     softmax over S per batch. bv cancels in softmax and is dropped.
// grid 32, 256 threads, 8 elems/thread.
// ---------------------------------------------------------------------------
__global__ __launch_bounds__(256)
void k3_softmax() {
    __shared__ float red[256];
    const int b = blockIdx.x, t = threadIdx.x;

    float sc[8];
    float mx = -1e30f;
    #pragma unroll
    for (int i = 0; i < 8; i++) {
        const int s = t + 256 * i;
        float v0 = 0.f;
        #pragma unroll
        for (int nt = 0; nt < NTILES; nt++)
            v0 += g_partials[(size_t)nt * MTOT + b * SEQ + s];
        sc[i] = v0;
        mx = fmaxf(mx, v0);
    }
    red[t] = mx; __syncthreads();
    for (int o = 128; o > 0; o >>= 1) {
        if (t < o) red[t] = fmaxf(red[t], red[t + o]);
        __syncthreads();
    }
    mx = red[0]; __syncthreads();

    float sum = 0.f;
    #pragma unroll
    for (int i = 0; i < 8; i++) { sc[i] = expf(sc[i] - mx); sum += sc[i]; }
    red[t] = sum; __syncthreads();
    for (int o = 128; o > 0; o >>= 1) {
        if (t < o) red[t] += red[t + o];
        __syncthreads();
    }
    const float inv = 1.f / red[0];
    #pragma unroll
    for (int i = 0; i < 8; i++)
        g_attn[b * SEQ + t + 256 * i] = sc[i] * inv;
}

// ---------------------------------------------------------------------------
// K4: context[b][e] = sum_s attn[b][s] * enc[b][s][e]   (memory-bound GEMV)
// grid (4, 32), 256 threads; 8 independent accumulators for MLP.
// ---------------------------------------------------------------------------
__global__ __launch_bounds__(256)
void k4_context(const float* __restrict__ enc, float* __restrict__ out) {
    __shared__ float sat[SEQ];
    const int b = blockIdx.y;
    const int e = blockIdx.x * 256 + threadIdx.x;
    for (int i = threadIdx.x; i < SEQ; i += 256) sat[i] = g_attn[b * SEQ + i];
    __syncthreads();

    const float* ep = enc + ((size_t)b * SEQ) * ENCD + e;
    float a0 = 0, a1 = 0, a2 = 0, a3 = 0, a4 = 0, a5 = 0, a6 = 0, a7 = 0;
    for (int s = 0; s < SEQ; s += 8) {
        a0 += sat[s + 0] * ep[(size_t)(s + 0) * ENCD];
        a1 += sat[s + 1] * ep[(size_t)(s + 1) * ENCD];
        a2 += sat[s + 2] * ep[(size_t)(s + 2) * ENCD];
        a3 += sat[s + 3] * ep[(size_t)(s + 3) * ENCD];
        a4 += sat[s + 4] * ep[(size_t)(s + 4) * ENCD];
        a5 += sat[s + 5] * ep[(size_t)(s + 5) * ENCD];
        a6 += sat[s + 6] * ep[(size_t)(s + 6) * ENCD];
        a7 += sat[s + 7] * ep[(size_t)(s + 7) * ENCD];
    }
    out[b * ENCD + e] = ((a0 + a1) + (a2 + a3)) + ((a4 + a5) + (a6 + a7));
}

// ---------------------------------------------------------------------------
extern "C" void kernel_launch(void* const* d_in, const int* in_sizes, int n_in,
                              void* d_out, int out_size) {
    const float* enc = (const float*)d_in[0];   // [32, 2048, 1024]
    const float* dec = (const float*)d_in[1];   // [32, 1, 1024]
    const float* w1  = (const float*)d_in[2];   // [1024, 1024]
    const float* b1  = (const float*)d_in[3];   // [1024]
    const float* w2  = (const float*)d_in[4];   // [1024, 1024]
    const float* b2  = (const float*)d_in[5];   // [1024]
    const float* v   = (const float*)d_in[6];   // [1024, 1]
    // d_in[7] = bv: shifts all scores equally -> cancels in softmax.
    float* out = (float*)d_out;                 // [32, 1024] fp32

    k1_query<<<32, 256>>>(dec, w2, b1, b2);
    k2_scores<<<dim3(512, NTILES), 256>>>(enc, w1, v);
    k3_softmax<<<32, 256>>>();
    k4_context<<<dim3(4, 32), 256>>>(enc, out);
}

// round 3
// speedup vs baseline: 3.8335x; 3.8335x over previous
#include <cuda_runtime.h>
#include <math.h>
#include <stdint.h>

#define ENCD   1024
#define BATCH  32
#define SEQ    2048
#define MTOT   (BATCH * SEQ)   // 65536
#define NTILES 8               // 1024/128 column tiles of the score GEMM
#define KS     16              // k-chunk per smem stage

// Scratch (static device arrays: no allocation allowed).
__device__ float g_q[BATCH * ENCD];            // q'[b][e] = dec@w2 + b2 + b1
__device__ float g_partials[NTILES * MTOT];    // per-ntile partial scores
__device__ float g_attn[MTOT];                 // softmax weights
__device__ float g_ctx[4][BATCH * ENCD];       // k4 s-chunk partial contexts

// ---------------------------------------------------------------------------
__device__ __forceinline__ uint32_t f2tf32(float x) {
    uint32_t r; asm("cvt.rna.tf32.f32 %0, %1;" : "=r"(r) : "f"(x)); return r;
}
__device__ __forceinline__ void mma_tf32(float* d, const uint32_t* a, const uint32_t* b) {
    asm volatile(
        "mma.sync.aligned.m16n8k8.row.col.f32.tf32.tf32.f32 "
        "{%0,%1,%2,%3},{%4,%5,%6,%7},{%8,%9},{%0,%1,%2,%3};"
        : "+f"(d[0]), "+f"(d[1]), "+f"(d[2]), "+f"(d[3])
        : "r"(a[0]), "r"(a[1]), "r"(a[2]), "r"(a[3]), "r"(b[0]), "r"(b[1]));
}

// ---------------------------------------------------------------------------
// K1: q'[b][e] = dec[b]@w2 + b2 + b1   (unchanged, not a bottleneck)
// ---------------------------------------------------------------------------
__global__ __launch_bounds__(256)
void k1_query(const float* __restrict__ dec, const float* __restrict__ w2,
              const float* __restrict__ b1, const float* __restrict__ b2) {
    __shared__ float sdec[ENCD];
    const int b = blockIdx.x;
    for (int i = threadIdx.x; i < ENCD; i += 256) sdec[i] = dec[b * ENCD + i];
    __syncthreads();

    float acc[4] = {0.f, 0.f, 0.f, 0.f};
    const int e0 = threadIdx.x;
    for (int d = 0; d < ENCD; d++) {
        const float dv = sdec[d];
        const float* wrow = w2 + (size_t)d * ENCD;
        #pragma unroll
        for (int c = 0; c < 4; c++) acc[c] += dv * wrow[e0 + 256 * c];
    }
    #pragma unroll
    for (int c = 0; c < 4; c++) {
        const int e = e0 + 256 * c;
        g_q[b * ENCD + e] = acc[c] + b1[e] + b2[e];
    }
}

// ---------------------------------------------------------------------------
// K2: fused score GEMM on tf32 tensor cores.
//   C-tile 128x128, K=1024, double-buffered smem, 8 warps in 2(M)x4(N),
//   each warp 64x32 via 4x4 m16n8k8 fragments. Epilogue: tanh + v-dot,
//   deterministic quad-shuffle + smem reduction, per-ntile partial out.
// grid (512, 8), 256 threads.
// ---------------------------------------------------------------------------
__global__ __launch_bounds__(256, 2)
void k2_scores(const float* __restrict__ enc, const float* __restrict__ w1,
               const float* __restrict__ v) {
    __shared__ uint32_t As[2][KS][136];   // A^T (k-major), +8 pad: frag loads bank-free
    __shared__ uint32_t Bs[2][KS][136];   // B   (k-major), +8 pad
    __shared__ float qs[128], vs[128];
    __shared__ float sredN[4][128];

    const int m0 = blockIdx.x * 128;
    const int nt = blockIdx.y, n0 = nt * 128;
    const int b  = m0 / SEQ;              // SEQ % 128 == 0
    const int t  = threadIdx.x;
    const int lane = t & 31, w = t >> 5;
    const int wm = w & 1, wn = w >> 1;    // warp grid 2 x 4
    const int g = lane >> 2, c = lane & 3;

    if (t < 128) { qs[t] = g_q[b * ENCD + n0 + t]; vs[t] = v[n0 + t]; }

    // A stage loads: 128 rows x 16 k = 512 float4, 2/thread.
    const int arow0 = t >> 2, akp = t & 3;
    const int arow1 = (t + 256) >> 2;
    const float4* encv = (const float4*)(enc + (size_t)m0 * ENCD);
    // B stage loads: 16 rows x 128 = 512 float4, 2/thread.
    const int bkr0 = t >> 5, bnv = t & 31, bkr1 = bkr0 + 8;
    const float4* w1v = (const float4*)w1;
    const int ncol4 = (n0 >> 2) + bnv;

    float acc[4][4][4];
    #pragma unroll
    for (int mi = 0; mi < 4; mi++)
        #pragma unroll
        for (int ni = 0; ni < 4; ni++)
            #pragma unroll
            for (int r = 0; r < 4; r++) acc[mi][ni][r] = 0.f;

    // Prologue: stage 0 (k0 = 0)
    {
        float4 ra0 = encv[arow0 * 256 + akp];
        float4 ra1 = encv[arow1 * 256 + akp];
        float4 rb0 = w1v[(size_t)bkr0 * 256 + ncol4];
        float4 rb1 = w1v[(size_t)bkr1 * 256 + ncol4];
        As[0][akp * 4 + 0][arow0] = f2tf32(ra0.x);
        As[0][akp * 4 + 1][arow0] = f2tf32(ra0.y);
        As[0][akp * 4 + 2][arow0] = f2tf32(ra0.z);
        As[0][akp * 4 + 3][arow0] = f2tf32(ra0.w);
        As[0][akp * 4 + 0][arow1] = f2tf32(ra1.x);
        As[0][akp * 4 + 1][arow1] = f2tf32(ra1.y);
        As[0][akp * 4 + 2][arow1] = f2tf32(ra1.z);
        As[0][akp * 4 + 3][arow1] = f2tf32(ra1.w);
        uint4 ub0 = make_uint4(f2tf32(rb0.x), f2tf32(rb0.y), f2tf32(rb0.z), f2tf32(rb0.w));
        uint4 ub1 = make_uint4(f2tf32(rb1.x), f2tf32(rb1.y), f2tf32(rb1.z), f2tf32(rb1.w));
        *(uint4*)&Bs[0][bkr0][bnv * 4] = ub0;
        *(uint4*)&Bs[0][bkr1][bnv * 4] = ub1;
    }
    __syncthreads();

    for (int ks = 0; ks < 64; ks++) {
        const int cur = ks & 1, nxt = cur ^ 1;
        float4 ra0, ra1, rb0, rb1;
        if (ks < 63) {
            const int k0 = (ks + 1) * KS;
            ra0 = encv[arow0 * 256 + (k0 >> 2) + akp];
            ra1 = encv[arow1 * 256 + (k0 >> 2) + akp];
            rb0 = w1v[(size_t)(k0 + bkr0) * 256 + ncol4];
            rb1 = w1v[(size_t)(k0 + bkr1) * 256 + ncol4];
        }
        #pragma unroll
        for (int kk = 0; kk < KS; kk += 8) {
            uint32_t af[4][4], bf[4][2];
            #pragma unroll
            for (int mi = 0; mi < 4; mi++) {
                const int mb = wm * 64 + mi * 16 + g;
                af[mi][0] = As[cur][kk + c][mb];
                af[mi][1] = As[cur][kk + c][mb + 8];
                af[mi][2] = As[cur][kk + c + 4][mb];
                af[mi][3] = As[cur][kk + c + 4][mb + 8];
            }
            #pragma unroll
            for (int ni = 0; ni < 4; ni++) {
                const int nb = wn * 32 + ni * 8 + g;
                bf[ni][0] = Bs[cur][kk + c][nb];
                bf[ni][1] = Bs[cur][kk + c + 4][nb];
            }
            #pragma unroll
            for (int mi = 0; mi < 4; mi++)
                #pragma unroll
                for (int ni = 0; ni < 4; ni++)
                    mma_tf32(acc[mi][ni], af[mi], bf[ni]);
        }
        if (ks < 63) {
            As[nxt][akp * 4 + 0][arow0] = f2tf32(ra0.x);
            As[nxt][akp * 4 + 1][arow0] = f2tf32(ra0.y);
            As[nxt][akp * 4 + 2][arow0] = f2tf32(ra0.z);
            As[nxt][akp * 4 + 3][arow0] = f2tf32(ra0.w);
            As[nxt][akp * 4 + 0][arow1] = f2tf32(ra1.x);
            As[nxt][akp * 4 + 1][arow1] = f2tf32(ra1.y);
            As[nxt][akp * 4 + 2][arow1] = f2tf32(ra1.z);
            As[nxt][akp * 4 + 3][arow1] = f2tf32(ra1.w);
            uint4 ub0 = make_uint4(f2tf32(rb0.x), f2tf32(rb0.y), f2tf32(rb0.z), f2tf32(rb0.w));
            uint4 ub1 = make_uint4(f2tf32(rb1.x), f2tf32(rb1.y), f2tf32(rb1.z), f2tf32(rb1.w));
            *(uint4*)&Bs[nxt][bkr0][bnv * 4] = ub0;
            *(uint4*)&Bs[nxt][bkr1][bnv * 4] = ub1;
            __syncthreads();
        }
    }

    // Epilogue. C frag: c0=(row g, col 2c), c1=(g, 2c+1), c2=(g+8, 2c), c3=(g+8, 2c+1)
    float rs0[4], rs1[4];
    #pragma unroll
    for (int mi = 0; mi < 4; mi++) {
        float s0 = 0.f, s1 = 0.f;
        #pragma unroll
        for (int ni = 0; ni < 4; ni++) {
            const int n_ = wn * 32 + ni * 8 + c * 2;
            const float q0 = qs[n_], q1 = qs[n_ + 1];
            const float v0 = vs[n_], v1 = vs[n_ + 1];
            s0 += tanhf(acc[mi][ni][0] + q0) * v0 + tanhf(acc[mi][ni][1] + q1) * v1;
            s1 += tanhf(acc[mi][ni][2] + q0) * v0 + tanhf(acc[mi][ni][3] + q1) * v1;
        }
        s0 += __shfl_xor_sync(0xffffffffu, s0, 1);
        s0 += __shfl_xor_sync(0xffffffffu, s0, 2);
        s1 += __shfl_xor_sync(0xffffffffu, s1, 1);
        s1 += __shfl_xor_sync(0xffffffffu, s1, 2);
        rs0[mi] = s0; rs1[mi] = s1;
    }
    if (c == 0) {
        #pragma unroll
        for (int mi = 0; mi < 4; mi++) {
            sredN[wn][wm * 64 + mi * 16 + g]     = rs0[mi];
            sredN[wn][wm * 64 + mi * 16 + g + 8] = rs1[mi];
        }
    }
    __syncthreads();
    if (t < 128)
        g_partials[(size_t)nt * MTOT + m0 + t] =
            (sredN[0][t] + sredN[1][t]) + (sredN[2][t] + sredN[3][t]);
}

// ---------------------------------------------------------------------------
// K3: sum 8 partials (fixed order -> deterministic), softmax over S per batch.
// ---------------------------------------------------------------------------
__global__ __launch_bounds__(256)
void k3_softmax() {
    __shared__ float red[256];
    const int b = blockIdx.x, t = threadIdx.x;

    float sc[8];
    float mx = -1e30f;
    #pragma unroll
    for (int i = 0; i < 8; i++) {
        const int s = t + 256 * i;
        float v0 = 0.f;
        #pragma unroll
        for (int nt = 0; nt < NTILES; nt++)
            v0 += g_partials[(size_t)nt * MTOT + b * SEQ + s];
        sc[i] = v0;
        mx = fmaxf(mx, v0);
    }
    red[t] = mx; __syncthreads();
    for (int o = 128; o > 0; o >>= 1) {
        if (t < o) red[t] = fmaxf(red[t], red[t + o]);
        __syncthreads();
    }
    mx = red[0]; __syncthreads();

    float sum = 0.f;
    #pragma unroll
    for (int i = 0; i < 8; i++) { sc[i] = expf(sc[i] - mx); sum += sc[i]; }
    red[t] = sum; __syncthreads();
    for (int o = 128; o > 0; o >>= 1) {
        if (t < o) red[t] += red[t + o];
        __syncthreads();
    }
    const float inv = 1.f / red[0];
    #pragma unroll
    for (int i = 0; i < 8; i++)
        g_attn[b * SEQ + t + 256 * i] = sc[i] * inv;
}

// ---------------------------------------------------------------------------
// K4: partial context over an S-chunk of 512. grid (4, 32, 4), 256 thr.
// ---------------------------------------------------------------------------
__global__ __launch_bounds__(256)
void k4_context(const float* __restrict__ enc) {
    __shared__ float sat[512];
    const int b  = blockIdx.y;
    const int sc = blockIdx.z;
    const int e  = blockIdx.x * 256 + threadIdx.x;
    const int sbase = sc * 512;
    for (int i = threadIdx.x; i < 512; i += 256) sat[i] = g_attn[b * SEQ + sbase + i];
    __syncthreads();

    const float* ep = enc + ((size_t)b * SEQ + sbase) * ENCD + e;
    float a0 = 0, a1 = 0, a2 = 0, a3 = 0, a4 = 0, a5 = 0, a6 = 0, a7 = 0;
    for (int s = 0; s < 512; s += 8) {
        a0 += sat[s + 0] * ep[(size_t)(s + 0) * ENCD];
        a1 += sat[s + 1] * ep[(size_t)(s + 1) * ENCD];
        a2 += sat[s + 2] * ep[(size_t)(s + 2) * ENCD];
        a3 += sat[s + 3] * ep[(size_t)(s + 3) * ENCD];
        a4 += sat[s + 4] * ep[(size_t)(s + 4) * ENCD];
        a5 += sat[s + 5] * ep[(size_t)(s + 5) * ENCD];
        a6 += sat[s + 6] * ep[(size_t)(s + 6) * ENCD];
        a7 += sat[s + 7] * ep[(size_t)(s + 7) * ENCD];
    }
    g_ctx[sc][b * ENCD + e] = ((a0 + a1) + (a2 + a3)) + ((a4 + a5) + (a6 + a7));
}

// K5: sum the 4 s-chunk partials in fixed order. grid 128, 256 thr.
__global__ __launch_bounds__(256)
void k5_reduce(float* __restrict__ out) {
    const int i = blockIdx.x * 256 + threadIdx.x;   // 0..32767
    out[i] = (g_ctx[0][i] + g_ctx[1][i]) + (g_ctx[2][i] + g_ctx[3][i]);
}

// ---------------------------------------------------------------------------
extern "C" void kernel_launch(void* const* d_in, const int* in_sizes, int n_in,
                              void* d_out, int out_size) {
    const float* enc = (const float*)d_in[0];   // [32, 2048, 1024]
    const float* dec = (const float*)d_in[1];   // [32, 1, 1024]
    const float* w1  = (const float*)d_in[2];   // [1024, 1024]
    const float* b1  = (const float*)d_in[3];   // [1024]
    const float* w2  = (const float*)d_in[4];   // [1024, 1024]
    const float* b2  = (const float*)d_in[5];   // [1024]
    const float* v   = (const float*)d_in[6];   // [1024, 1]
    // d_in[7] = bv cancels in softmax.
    float* out = (float*)d_out;                 // [32, 1024] fp32

    k1_query<<<32, 256>>>(dec, w2, b1, b2);
    k2_scores<<<dim3(512, NTILES), 256>>>(enc, w1, v);
    k3_softmax<<<32, 256>>>();
    k4_context<<<dim3(4, 32, 4), 256>>>(enc);
    k5_reduce<<<128, 256>>>(out);
}